// round 10
// baseline (speedup 1.0000x reference)
#include <cuda_runtime.h>

#define BATCH 4
#define NP    4096
#define MQ    4096
#define CC    16
#define KMAX  128
#define MAXCELLS (96*96*96 + 1)

// Output layout (float elements)
#define OFF_LOCS 0
#define OFF_DATA (BATCH*NP*3)                       // 49152
#define OFF_IDXS (OFF_DATA + BATCH*NP*CC)           // 311296
#define OFF_NEI  (OFF_IDXS + BATCH*NP)              // 327680

// ---- device scratch (no allocations allowed) ----
__device__ float  g_low[BATCH][3];
__device__ float  g_gdimf[BATCH][3];
__device__ int    g_stride[BATCH][3];
__device__ float4 g_p4[BATCH * NP];      // reordered particles: x,y,z,|p|^2
__device__ int    g_cellstart[BATCH][MAXCELLS];

// Dynamic smem for k_prep: sl[NP*3] floats + sk[NP] uints
#define SMEM_PREP ((NP*3)*4 + NP*4)

// ---------------------------------------------------------------------------
// Kernel 1: bounds + grid params + keys + cell_start table + counting-sort
// scatter, all fused. grid = (64, BATCH), 256 threads (8 warps).
// Every block redundantly recomputes its batch's bounds/keys (min/max exactly
// order-independent -> bit-identical across blocks). Then ONE WARP PER CELL:
//   pass 1: base = #{keys < c<<12}  (== lower_bound == cell_start[c], stored)
//   pass 2: scan keys in index order; ballot over "cell == c"; matched lane
//           gets stable rank = base + running count and scatters particle i.
// Exact: keys are unique (cell<<12)|i, so this rank equals #{key_j < key_i}.
// ---------------------------------------------------------------------------
__global__ __launch_bounds__(256) void k_prep(const float* __restrict__ locs,
                                              const float* __restrict__ data,
                                              float* __restrict__ out) {
    extern __shared__ float sdyn[];
    float*        sl = sdyn;                          // [NP*3]
    unsigned int* sk = (unsigned int*)(sdyn + NP*3);  // [NP]

    __shared__ float swmn[8][3], swmx[8][3];
    __shared__ float s_low[3], s_gdimf[3];
    __shared__ int   s_stride[3];
    __shared__ int   s_ncell;

    const int b = blockIdx.y;
    const int t = threadIdx.x;

    // ---- phase 0: stage batch locs into smem (coalesced uint4) ----
    {
        const uint4* src = (const uint4*)(locs + (size_t)b * NP * 3);
        uint4* dstv = (uint4*)sl;
        #pragma unroll
        for (int j = t; j < NP * 3 / 4; j += 256)
            dstv[j] = src[j];
    }
    __syncthreads();

    // ---- phase 1: batch bounds ----
    float mn[3] = {1e30f, 1e30f, 1e30f};
    float mx[3] = {-1e30f, -1e30f, -1e30f};
    for (int i = t; i < NP; i += 256) {
        #pragma unroll
        for (int d = 0; d < 3; d++) {
            float v = sl[i * 3 + d];
            mn[d] = fminf(mn[d], v);
            mx[d] = fmaxf(mx[d], v);
        }
    }
    #pragma unroll
    for (int o = 16; o > 0; o >>= 1) {
        #pragma unroll
        for (int d = 0; d < 3; d++) {
            mn[d] = fminf(mn[d], __shfl_xor_sync(0xffffffffu, mn[d], o));
            mx[d] = fmaxf(mx[d], __shfl_xor_sync(0xffffffffu, mx[d], o));
        }
    }
    const int wid = t >> 5, lid = t & 31;
    if (lid == 0) {
        #pragma unroll
        for (int d = 0; d < 3; d++) { swmn[wid][d] = mn[d]; swmx[wid][d] = mx[d]; }
    }
    __syncthreads();
    if (t == 0) {
        #pragma unroll
        for (int w = 1; w < 8; w++) {
            #pragma unroll
            for (int d = 0; d < 3; d++) {
                swmn[0][d] = fminf(swmn[0][d], swmn[w][d]);
                swmx[0][d] = fmaxf(swmx[0][d], swmx[w][d]);
            }
        }
        int gd[3];
        #pragma unroll
        for (int d = 0; d < 3; d++) {
            float lo = swmn[0][d], up = swmx[0][d];
            float diff = __fsub_rn(up, lo);
            float gdf  = ceilf(fminf(fmaxf(__fdiv_rn(diff, 0.14f), 0.0f), 96.0f));
            float center = __fmul_rn(__fadd_rn(lo, up), 0.5f);
            float half   = __fmul_rn(__fmul_rn(gdf, 0.14f), 0.5f);
            float low2   = __fsub_rn(center, half);
            s_low[d] = low2;
            s_gdimf[d] = gdf;
            int gi = (int)gdf;
            gd[d] = gi > 1 ? gi : 1;
        }
        s_stride[0] = gd[1] * gd[2]; s_stride[1] = gd[2]; s_stride[2] = 1;
        s_ncell = gd[0] * gd[1] * gd[2];
        if (blockIdx.x == 0) {       // publish for k_neighbors
            #pragma unroll
            for (int d = 0; d < 3; d++) {
                g_low[b][d]    = s_low[d];
                g_gdimf[b][d]  = s_gdimf[d];
                g_stride[b][d] = s_stride[d];
            }
        }
    }
    __syncthreads();

    // ---- phase 2: keys. key = (cell_id << 12) | particle_index ----
    for (int i = t; i < NP; i += 256) {
        unsigned int id = 0;
        #pragma unroll
        for (int d = 0; d < 3; d++) {
            float c = floorf(__fdiv_rn(__fsub_rn(sl[i * 3 + d], s_low[d]), 0.14f));
            c = fminf(fmaxf(c, 0.0f), __fsub_rn(s_gdimf[d], 1.0f));
            id += (unsigned int)((int)c * s_stride[d]);
        }
        sk[i] = (id << 12) | (unsigned int)i;
    }
    __syncthreads();

    // ---- phase 3: one warp per cell c: cell_start + counting-sort scatter.
    {
        const int wg    = blockIdx.x * 8 + wid;      // 0..511 within batch
        const int ncell = s_ncell;
        const uint4* k4 = (const uint4*)sk;
        const float4* d4 = (const float4*)data;      // CC=16 -> 4 float4/row
        float4* o4 = (float4*)(out + OFF_DATA);

        for (int c = wg; c <= ncell; c += 512) {
            const unsigned int clo = (unsigned int)c << 12;

            // pass 1: base = #{keys < c<<12}
            int cnt = 0;
            #pragma unroll 8
            for (int j = 0; j < NP / 128; j++) {
                uint4 v = k4[lid + j * 32];
                cnt += (v.x < clo) + (v.y < clo) + (v.z < clo) + (v.w < clo);
            }
            #pragma unroll
            for (int o = 16; o > 0; o >>= 1)
                cnt += __shfl_xor_sync(0xffffffffu, cnt, o);
            if (lid == 0) g_cellstart[b][c] = cnt;
            if (c == ncell) continue;                // boundary entry only

            // pass 2: stable within-cell offsets + scatter
            const unsigned int chi = clo + (1u << 12);
            int run = cnt;
            for (int j0 = 0; j0 < NP; j0 += 32) {
                unsigned int key = sk[j0 + lid];
                bool match = (key >= clo) & (key < chi);
                unsigned mask = __ballot_sync(0xffffffffu, match);
                if (match) {
                    int r = run + __popc(mask & ((1u << lid) - 1));
                    int i = (int)(key & 0xFFFu);
                    const int src = b * NP + i;
                    const int dst = b * NP + r;

                    float x = sl[i * 3 + 0], y = sl[i * 3 + 1], z = sl[i * 3 + 2];
                    float pn = x * x + y * y + z * z;

                    out[OFF_LOCS + (size_t)dst * 3 + 0] = x;
                    out[OFF_LOCS + (size_t)dst * 3 + 1] = y;
                    out[OFF_LOCS + (size_t)dst * 3 + 2] = z;
                    g_p4[dst] = make_float4(x, y, z, pn);
                    out[OFF_IDXS + dst] = (float)i;
                    #pragma unroll
                    for (int k = 0; k < 4; k++)
                        o4[(size_t)dst * 4 + k] = d4[(size_t)src * 4 + k];
                }
                run += __popc(mask);
            }
        }
    }
}

// ---------------------------------------------------------------------------
// Kernel 2: radius search, one WARP per query, compact candidate stream.
// Row ranges come straight from the cell_start table (one load per lane).
// Warp prefix-scan concatenates the <=9 contiguous (x,y) row ranges into one
// stream handled by a single ballot loop. Stream order == ascending sorted
// index -> neighbor order matches the reference exactly.
// ---------------------------------------------------------------------------
__global__ __launch_bounds__(256) void k_neighbors(const float* __restrict__ qlocs,
                                                   float* __restrict__ out) {
    __shared__ int spre[8][10];   // exclusive prefix: spre[w][r], [nr] = T
    __shared__ int soff[8][9];    // soff[w][r] = start_r - pre_r

    const int b    = blockIdx.y;
    const int w    = threadIdx.x >> 5;
    const int lane = threadIdx.x & 31;
    const int m    = blockIdx.x * 8 + w;

    const float* q = qlocs + (size_t)(b * MQ + m) * 3;
    const float q0 = __ldg(&q[0]), q1 = __ldg(&q[1]), q2 = __ldg(&q[2]);
    const float qn = q0 * q0 + q1 * q1 + q2 * q2;
    const float R2 = (float)(0.14 * 0.14);

    int cq[3], gd[3];
    #pragma unroll
    for (int d = 0; d < 3; d++) {
        float qd = (d == 0) ? q0 : (d == 1) ? q1 : q2;
        float c = floorf(__fdiv_rn(__fsub_rn(qd, g_low[b][d]), 0.14f));
        int gi = (int)g_gdimf[b][d];
        gd[d] = gi > 1 ? gi : 1;
        int ci = (int)c;
        cq[d] = min(max(ci, 0), gd[d] - 1);
    }
    const int s0 = g_stride[b][0];
    const int s1 = g_stride[b][1];
    const int xlo = max(cq[0] - 1, 0), xhi = min(cq[0] + 1, gd[0] - 1);
    const int ylo = max(cq[1] - 1, 0), yhi = min(cq[1] + 1, gd[1] - 1);
    const int zlo = max(cq[2] - 1, 0), zhi = min(cq[2] + 1, gd[2] - 1);

    const int ny = yhi - ylo + 1;
    const int nr = (xhi - xlo + 1) * ny;

    // One table load per lane: lane r < nr -> row-range start, lane r+nr -> end.
    int val = 0;
    if (lane < 2 * nr) {
        int rr = (lane < nr) ? lane : lane - nr;
        // exact rr/ny for rr<=8, ny in {1,2,3} without integer-div subroutine
        int dv = (ny == 3) ? ((rr * 11) >> 5) : ((ny == 2) ? (rr >> 1) : rr);
        int md = rr - dv * ny;
        int cell = (xlo + dv) * s0 + (ylo + md) * s1
                 + ((lane < nr) ? zlo : (zhi + 1));
        val = __ldg(&g_cellstart[b][cell]);
    }

    // Concatenate ranges: prefix-scan the lengths across the warp.
    int e_r = __shfl_sync(0xffffffffu, val, lane + nr);
    int len = (lane < nr) ? (e_r - val) : 0;
    int inc = len;
    #pragma unroll
    for (int o = 1; o < 32; o <<= 1) {
        int v = __shfl_up_sync(0xffffffffu, inc, o);
        if (lane >= o) inc += v;
    }
    const int T = __shfl_sync(0xffffffffu, inc, 31);
    if (lane < nr) {
        spre[w][lane + 1] = inc;
        soff[w][lane] = val - (inc - len);
    }
    if (lane == 0) spre[w][0] = 0;
    __syncwarp();

    const float4* P = g_p4 + b * NP;
    float* no = out + OFF_NEI + (size_t)(b * MQ + m) * KMAX;

    int cnt = 0;
    int r = 0;
    for (int k0 = 0; k0 < T; k0 += 32) {
        const int k = k0 + lane;
        bool hit = false;
        int j = 0;
        if (k < T) {
            while (k >= spre[w][r + 1]) r++;
            j = k + soff[w][r];
            float4 p = __ldg(&P[j]);
            float cross = q0 * p.x + q1 * p.y + q2 * p.z;
            float d2 = (qn + p.w) - 2.0f * cross;
            hit = d2 <= R2;
        }
        unsigned mask = __ballot_sync(0xffffffffu, hit);
        if (hit) {
            int pos = cnt + __popc(mask & ((1u << lane) - 1));
            if (pos < KMAX) no[pos] = (float)j;
        }
        cnt += __popc(mask);
        if (cnt >= KMAX) break;
    }

    // ---- fill tail with -1: scalar to 4-alignment, then one float4 store ----
    const int s = min(cnt, KMAX);
    const int aligned = (s + 3) & ~3;
    if (lane < aligned - s) no[s + lane] = -1.0f;
    const int q4 = (aligned >> 2) + lane;
    if (q4 < KMAX / 4)
        ((float4*)no)[q4] = make_float4(-1.0f, -1.0f, -1.0f, -1.0f);
}

// ---------------------------------------------------------------------------
extern "C" void kernel_launch(void* const* d_in, const int* in_sizes, int n_in,
                              void* d_out, int out_size) {
    const float* locs  = (const float*)d_in[0];   // [B,N,3]
    const float* data  = (const float*)d_in[1];   // [B,N,16]
    const float* qlocs = (const float*)d_in[2];   // [B,M,3]
    float* out = (float*)d_out;

    cudaFuncSetAttribute(k_prep,
                         cudaFuncAttributeMaxDynamicSharedMemorySize,
                         SMEM_PREP);
    dim3 g1(64, BATCH);
    k_prep<<<g1, 256, SMEM_PREP>>>(locs, data, out);

    dim3 g2(MQ / 8, BATCH);     // 8 warps per block, one warp per query
    k_neighbors<<<g2, 256>>>(qlocs, out);
}

// round 11
// speedup vs baseline: 1.1042x; 1.1042x over previous
#include <cuda_runtime.h>

#define BATCH 4
#define NP    4096
#define MQ    4096
#define CC    16
#define KMAX  128
#define MAXCELLS (96*96*96 + 1)

// Output layout (float elements)
#define OFF_LOCS 0
#define OFF_DATA (BATCH*NP*3)                       // 49152
#define OFF_IDXS (OFF_DATA + BATCH*NP*CC)           // 311296
#define OFF_NEI  (OFF_IDXS + BATCH*NP)              // 327680

// ---- device scratch (no allocations allowed) ----
__device__ float  g_low[BATCH][3];
__device__ float  g_gdimf[BATCH][3];
__device__ int    g_stride[BATCH][3];
__device__ float4 g_p4[BATCH * NP];      // reordered particles: x,y,z,|p|^2
__device__ int    g_cellstart[BATCH][MAXCELLS];

// Dynamic smem for k_prep: sl[NP*3] floats + sk[NP] uints + sp[256] ints
#define SMEM_PREP ((NP*3)*4 + NP*4 + 256*4)

// ---------------------------------------------------------------------------
// Kernel 1 (R9-proven): bounds + grid params + keys + cell_start table +
// split rank sort + scatter. grid = (64, BATCH), 256 threads, 4 thr/particle.
// Each block ends with griddepcontrol.launch_dependents AFTER its stores so
// the PDL-launched k_neighbors sees them once its griddepcontrol.wait passes.
// ---------------------------------------------------------------------------
__global__ __launch_bounds__(256) void k_prep(const float* __restrict__ locs,
                                              const float* __restrict__ data,
                                              float* __restrict__ out) {
    extern __shared__ float sdyn[];
    float*        sl = sdyn;                          // [NP*3]
    unsigned int* sk = (unsigned int*)(sdyn + NP*3);  // [NP]
    int*          sp = (int*)(sk + NP);               // [256]

    __shared__ float swmn[8][3], swmx[8][3];
    __shared__ float s_low[3], s_gdimf[3];
    __shared__ int   s_stride[3];
    __shared__ int   s_ncell;

    const int b = blockIdx.y;
    const int t = threadIdx.x;

    // ---- phase 0: stage batch locs into smem (coalesced uint4) ----
    {
        const uint4* src = (const uint4*)(locs + (size_t)b * NP * 3);
        uint4* dstv = (uint4*)sl;
        #pragma unroll
        for (int j = t; j < NP * 3 / 4; j += 256)
            dstv[j] = src[j];
    }
    __syncthreads();

    // ---- phase 1: batch bounds ----
    float mn[3] = {1e30f, 1e30f, 1e30f};
    float mx[3] = {-1e30f, -1e30f, -1e30f};
    for (int i = t; i < NP; i += 256) {
        #pragma unroll
        for (int d = 0; d < 3; d++) {
            float v = sl[i * 3 + d];
            mn[d] = fminf(mn[d], v);
            mx[d] = fmaxf(mx[d], v);
        }
    }
    #pragma unroll
    for (int o = 16; o > 0; o >>= 1) {
        #pragma unroll
        for (int d = 0; d < 3; d++) {
            mn[d] = fminf(mn[d], __shfl_xor_sync(0xffffffffu, mn[d], o));
            mx[d] = fmaxf(mx[d], __shfl_xor_sync(0xffffffffu, mx[d], o));
        }
    }
    const int wid = t >> 5, lid = t & 31;
    if (lid == 0) {
        #pragma unroll
        for (int d = 0; d < 3; d++) { swmn[wid][d] = mn[d]; swmx[wid][d] = mx[d]; }
    }
    __syncthreads();
    if (t == 0) {
        #pragma unroll
        for (int w = 1; w < 8; w++) {
            #pragma unroll
            for (int d = 0; d < 3; d++) {
                swmn[0][d] = fminf(swmn[0][d], swmn[w][d]);
                swmx[0][d] = fmaxf(swmx[0][d], swmx[w][d]);
            }
        }
        int gd[3];
        #pragma unroll
        for (int d = 0; d < 3; d++) {
            float lo = swmn[0][d], up = swmx[0][d];
            float diff = __fsub_rn(up, lo);
            float gdf  = ceilf(fminf(fmaxf(__fdiv_rn(diff, 0.14f), 0.0f), 96.0f));
            float center = __fmul_rn(__fadd_rn(lo, up), 0.5f);
            float half   = __fmul_rn(__fmul_rn(gdf, 0.14f), 0.5f);
            float low2   = __fsub_rn(center, half);
            s_low[d] = low2;
            s_gdimf[d] = gdf;
            int gi = (int)gdf;
            gd[d] = gi > 1 ? gi : 1;
        }
        s_stride[0] = gd[1] * gd[2]; s_stride[1] = gd[2]; s_stride[2] = 1;
        s_ncell = gd[0] * gd[1] * gd[2];
        if (blockIdx.x == 0) {       // publish for k_neighbors
            #pragma unroll
            for (int d = 0; d < 3; d++) {
                g_low[b][d]    = s_low[d];
                g_gdimf[b][d]  = s_gdimf[d];
                g_stride[b][d] = s_stride[d];
            }
        }
    }
    __syncthreads();

    // ---- phase 2: keys. key = (cell_id << 12) | particle_index ----
    for (int i = t; i < NP; i += 256) {
        unsigned int id = 0;
        #pragma unroll
        for (int d = 0; d < 3; d++) {
            float c = floorf(__fdiv_rn(__fsub_rn(sl[i * 3 + d], s_low[d]), 0.14f));
            c = fminf(fmaxf(c, 0.0f), __fsub_rn(s_gdimf[d], 1.0f));
            id += (unsigned int)((int)c * s_stride[d]);
        }
        sk[i] = (id << 12) | (unsigned int)i;
    }
    __syncthreads();

    // ---- phase 2.5: cell_start table. One warp per cell, strided across the
    // 512 warps of this batch's 64 blocks. 32 uint4 LDS + reduce per cell.
    {
        const int wg = blockIdx.x * 8 + wid;         // 0..511 within batch
        const int ncell = s_ncell;
        const uint4* k4 = (const uint4*)sk;
        for (int c = wg; c <= ncell; c += 512) {
            const unsigned int th = (unsigned int)c << 12;
            int cnt = 0;
            #pragma unroll 8
            for (int j = 0; j < NP / 128; j++) {
                uint4 v = k4[lid + j * 32];
                cnt += (v.x < th) + (v.y < th) + (v.z < th) + (v.w < th);
            }
            #pragma unroll
            for (int o = 16; o > 0; o >>= 1)
                cnt += __shfl_xor_sync(0xffffffffu, cnt, o);
            if (lid == 0) g_cellstart[b][c] = cnt;
        }
    }

    // ---- phase 3: split rank scan (4 threads per particle) ----
    const int il = t & 63;                        // particle slot in block
    const int i  = blockIdx.x * 64 + il;          // particle index in batch
    const unsigned int my = sk[i];
    {
        const uint4* k4 = (const uint4*)sk;
        const int base = (t >> 6) * (NP / 16);    // seg * 256 uint4s
        int r = 0;
        #pragma unroll 8
        for (int j = 0; j < NP / 16; j++) {
            uint4 v = k4[base + j];
            r += (v.x < my) + (v.y < my) + (v.z < my) + (v.w < my);
        }
        sp[t] = r;
    }
    __syncthreads();

    // ---- phase 4: scatter (first 64 threads) ----
    if (t < 64) {
        const int r   = sp[il] + sp[il + 64] + sp[il + 128] + sp[il + 192];
        const int src = b * NP + i;
        const int dst = b * NP + r;

        float x = sl[i * 3 + 0], y = sl[i * 3 + 1], z = sl[i * 3 + 2];
        float pn = x * x + y * y + z * z;

        out[OFF_LOCS + (size_t)dst * 3 + 0] = x;
        out[OFF_LOCS + (size_t)dst * 3 + 1] = y;
        out[OFF_LOCS + (size_t)dst * 3 + 2] = z;
        g_p4[dst] = make_float4(x, y, z, pn);
        out[OFF_IDXS + dst] = (float)i;

        const float4* d4 = (const float4*)data;   // CC=16 -> 4 float4 per row
        float4* o4 = (float4*)(out + OFF_DATA);
        #pragma unroll
        for (int k = 0; k < 4; k++)
            o4[(size_t)dst * 4 + k] = d4[(size_t)src * 4 + k];
    }

    // ---- PDL trigger: this block's stores are done; let dependents launch.
    __syncthreads();
    asm volatile("griddepcontrol.launch_dependents;");
}

// ---------------------------------------------------------------------------
// Kernel 2: radius search, one WARP per query, compact candidate stream.
// Launched with PDL: does its prep-independent preamble, then
// griddepcontrol.wait before touching anything k_prep produced.
// ---------------------------------------------------------------------------
__global__ __launch_bounds__(256) void k_neighbors(const float* __restrict__ qlocs,
                                                   float* __restrict__ out) {
    __shared__ int spre[8][10];   // exclusive prefix: spre[w][r], [nr] = T
    __shared__ int soff[8][9];    // soff[w][r] = start_r - pre_r

    const int b    = blockIdx.y;
    const int w    = threadIdx.x >> 5;
    const int lane = threadIdx.x & 31;
    const int m    = blockIdx.x * 8 + w;

    // prep-independent preamble (qlocs is a harness input, not prep output)
    const float* q = qlocs + (size_t)(b * MQ + m) * 3;
    const float q0 = __ldg(&q[0]), q1 = __ldg(&q[1]), q2 = __ldg(&q[2]);
    const float qn = q0 * q0 + q1 * q1 + q2 * q2;
    const float R2 = (float)(0.14 * 0.14);

    // wait for k_prep's stores to be visible
    asm volatile("griddepcontrol.wait;");

    int cq[3], gd[3];
    #pragma unroll
    for (int d = 0; d < 3; d++) {
        float qd = (d == 0) ? q0 : (d == 1) ? q1 : q2;
        float c = floorf(__fdiv_rn(__fsub_rn(qd, g_low[b][d]), 0.14f));
        int gi = (int)g_gdimf[b][d];
        gd[d] = gi > 1 ? gi : 1;
        int ci = (int)c;
        cq[d] = min(max(ci, 0), gd[d] - 1);
    }
    const int s0 = g_stride[b][0];
    const int s1 = g_stride[b][1];
    const int xlo = max(cq[0] - 1, 0), xhi = min(cq[0] + 1, gd[0] - 1);
    const int ylo = max(cq[1] - 1, 0), yhi = min(cq[1] + 1, gd[1] - 1);
    const int zlo = max(cq[2] - 1, 0), zhi = min(cq[2] + 1, gd[2] - 1);

    const int ny = yhi - ylo + 1;
    const int nr = (xhi - xlo + 1) * ny;

    // One table load per lane: lane r < nr -> row-range start, lane r+nr -> end.
    int val = 0;
    if (lane < 2 * nr) {
        int rr = (lane < nr) ? lane : lane - nr;
        // exact rr/ny for rr<=8, ny in {1,2,3} without integer-div subroutine
        int dv = (ny == 3) ? ((rr * 11) >> 5) : ((ny == 2) ? (rr >> 1) : rr);
        int md = rr - dv * ny;
        int cell = (xlo + dv) * s0 + (ylo + md) * s1
                 + ((lane < nr) ? zlo : (zhi + 1));
        val = __ldg(&g_cellstart[b][cell]);
    }

    // Concatenate ranges: prefix-scan the lengths across the warp.
    int e_r = __shfl_sync(0xffffffffu, val, lane + nr);
    int len = (lane < nr) ? (e_r - val) : 0;
    int inc = len;
    #pragma unroll
    for (int o = 1; o < 32; o <<= 1) {
        int v = __shfl_up_sync(0xffffffffu, inc, o);
        if (lane >= o) inc += v;
    }
    const int T = __shfl_sync(0xffffffffu, inc, 31);
    if (lane < nr) {
        spre[w][lane + 1] = inc;
        soff[w][lane] = val - (inc - len);
    }
    if (lane == 0) spre[w][0] = 0;
    __syncwarp();

    const float4* P = g_p4 + b * NP;
    float* no = out + OFF_NEI + (size_t)(b * MQ + m) * KMAX;

    int cnt = 0;
    int r = 0;
    for (int k0 = 0; k0 < T; k0 += 32) {
        const int k = k0 + lane;
        bool hit = false;
        int j = 0;
        if (k < T) {
            while (k >= spre[w][r + 1]) r++;
            j = k + soff[w][r];
            float4 p = __ldg(&P[j]);
            float cross = q0 * p.x + q1 * p.y + q2 * p.z;
            float d2 = (qn + p.w) - 2.0f * cross;
            hit = d2 <= R2;
        }
        unsigned mask = __ballot_sync(0xffffffffu, hit);
        if (hit) {
            int pos = cnt + __popc(mask & ((1u << lane) - 1));
            if (pos < KMAX) no[pos] = (float)j;
        }
        cnt += __popc(mask);
        if (cnt >= KMAX) break;
    }

    // ---- fill tail with -1: scalar to 4-alignment, then one float4 store ----
    const int s = min(cnt, KMAX);
    const int aligned = (s + 3) & ~3;
    if (lane < aligned - s) no[s + lane] = -1.0f;
    const int q4 = (aligned >> 2) + lane;
    if (q4 < KMAX / 4)
        ((float4*)no)[q4] = make_float4(-1.0f, -1.0f, -1.0f, -1.0f);
}

// ---------------------------------------------------------------------------
extern "C" void kernel_launch(void* const* d_in, const int* in_sizes, int n_in,
                              void* d_out, int out_size) {
    const float* locs  = (const float*)d_in[0];   // [B,N,3]
    const float* data  = (const float*)d_in[1];   // [B,N,16]
    const float* qlocs = (const float*)d_in[2];   // [B,M,3]
    float* out = (float*)d_out;

    cudaFuncSetAttribute(k_prep,
                         cudaFuncAttributeMaxDynamicSharedMemorySize,
                         SMEM_PREP);
    dim3 g1(64, BATCH);
    k_prep<<<g1, 256, SMEM_PREP>>>(locs, data, out);

    // k_neighbors with Programmatic Dependent Launch: overlaps its launch with
    // k_prep's tail; griddepcontrol.wait in-kernel enforces the dependency.
    {
        cudaLaunchConfig_t cfg = {};
        cfg.gridDim  = dim3(MQ / 8, BATCH);
        cfg.blockDim = dim3(256, 1, 1);
        cfg.dynamicSmemBytes = 0;
        cudaLaunchAttribute attrs[1];
        attrs[0].id = cudaLaunchAttributeProgrammaticStreamSerialization;
        attrs[0].val.programmaticStreamSerializationAllowed = 1;
        cfg.attrs = attrs;
        cfg.numAttrs = 1;
        cudaLaunchKernelEx(&cfg, k_neighbors, qlocs, out);
    }
}